// round 4
// baseline (speedup 1.0000x reference)
#include <cuda_runtime.h>
#include <cuda_bf16.h>
#include <cstdint>

// Problem constants
#define BB   64
#define LL   1024
#define ENC  512
#define ATTN 512
#define STRH 256
#define CELLH 512

// ---------------- scratch (no allocations allowed) ----------------
__device__ float g_bias[BB * ATTN];     // per-(b,a) bias = b_enc + a_str + a_cell
__device__ float g_scores[BB * LL];     // pre-softmax scores

// ---------------- f32x2 packed-FMA helpers (sm_100+) ----------------
__device__ __forceinline__ unsigned long long pack2(float x, float y) {
    unsigned long long r;
    asm("mov.b64 %0, {%1, %2};" : "=l"(r) : "f"(x), "f"(y));
    return r;
}
__device__ __forceinline__ void unpack2(unsigned long long v, float& lo, float& hi) {
    asm("mov.b64 {%0, %1}, %2;" : "=f"(lo), "=f"(hi) : "l"(v));
}
__device__ __forceinline__ void ffma2(unsigned long long& d, unsigned long long a,
                                      unsigned long long b) {
    asm("fma.rn.f32x2 %0, %1, %2, %0;" : "+l"(d) : "l"(a), "l"(b));
}

// =====================================================================
// Kernel A: bias[b][a] = b_enc[a] + str[b]@W_str[:,a] + b_str[a]
//                       + cell[b]@W_cell[:,a] + b_cell[a]
// grid = 64 blocks (b), 512 threads (a)
// =====================================================================
__global__ __launch_bounds__(512)
void bias_kernel(const float* __restrict__ str, const float* __restrict__ cell,
                 const float* __restrict__ Wstr, const float* __restrict__ bstr,
                 const float* __restrict__ Wcell, const float* __restrict__ bcell,
                 const float* __restrict__ benc)
{
    __shared__ float sh[STRH + CELLH];
    const int b = blockIdx.x;
    const int a = threadIdx.x;

    if (a < STRH) sh[a] = str[b * STRH + a];
    sh[STRH + a] = cell[b * CELLH + a];
    __syncthreads();

    float acc = benc[a] + bstr[a] + bcell[a];
#pragma unroll 8
    for (int e = 0; e < STRH; ++e)
        acc += sh[e] * Wstr[e * ATTN + a];
#pragma unroll 8
    for (int e = 0; e < CELLH; ++e)
        acc += sh[STRH + e] * Wcell[e * ATTN + a];

    g_bias[b * ATTN + a] = acc;
}

// =====================================================================
// Kernel B: fused GEMM + relu + W_comb reduction -> scores[b][l]
//   scores[b][l] = sum_a relu( x[b,l,:]@W_enc[:,a] + bias[b][a] ) * Wc[a] + b_comb
// Block tile: 64 L-rows x 128 N-cols per chunk (4 chunks cover ATTN=512), K=512.
// 256 threads, thread microtile 4(m) x 8(n) via f32x2 (m-pairs packed).
// x tile kept transposed in smem for the whole block; W double-buffered.
// =====================================================================
#define XT_STRIDE 66                    // 64 + 2 pad (even -> 8B-aligned LDS.64)
#define SM_XT     0                     // 512 * 66 floats
#define SM_WT     (512 * XT_STRIDE)     // 2 * 64 * 128 floats
#define SM_BIAS   (SM_WT + 2 * 64 * 128)
#define SM_WC     (SM_BIAS + ATTN)
#define SM_RED    (SM_WC + ATTN)        // 64 * 17 floats
#define SMEM_B_FLOATS (SM_RED + 64 * 17)
#define SMEM_B_BYTES  (SMEM_B_FLOATS * 4)   // 209,220 B < 227 KB

__global__ __launch_bounds__(256, 1)
void scores_kernel(const float* __restrict__ x, const float* __restrict__ W,
                   const float* __restrict__ Wc, const float* __restrict__ bcomb)
{
    extern __shared__ float sm[];
    float* xT     = sm + SM_XT;    // [512][XT_STRIDE]  (k-major, m contiguous)
    float* Wt     = sm + SM_WT;    // [2][64][128]
    float* bias_s = sm + SM_BIAS;  // [512]
    float* wc_s   = sm + SM_WC;    // [512]
    float* red    = sm + SM_RED;   // [64][17]

    const int b   = blockIdx.y;
    const int l0  = blockIdx.x * 64;
    const int tid = threadIdx.x;

    // ---- load x tile transposed: xT[e][m] = x[b][l0+m][e] ----
    const float4* xg = reinterpret_cast<const float4*>(
        x + ((size_t)b * LL + l0) * ENC);
#pragma unroll
    for (int it = 0; it < 32; ++it) {            // 64*128 float4 / 256 threads
        int idx = tid + it * 256;
        int l = idx >> 7;                         // 0..63
        int e4 = idx & 127;                       // 0..127
        float4 v = xg[l * 128 + e4];
        int e = e4 * 4;
        xT[(e + 0) * XT_STRIDE + l] = v.x;
        xT[(e + 1) * XT_STRIDE + l] = v.y;
        xT[(e + 2) * XT_STRIDE + l] = v.z;
        xT[(e + 3) * XT_STRIDE + l] = v.w;
    }
    // ---- bias / Wc into smem ----
#pragma unroll
    for (int i = tid; i < ATTN; i += 256) {
        bias_s[i] = g_bias[b * ATTN + i];
        wc_s[i]   = Wc[i];
    }

    const int ty = tid >> 4;          // 0..15  -> m group
    const int tx = tid & 15;          // 0..15  -> n group
    const int m0 = ty * 4;

    float s0 = 0.f, s1 = 0.f, s2 = 0.f, s3 = 0.f;

    const float4* Wg4 = reinterpret_cast<const float4*>(W);
    // per-thread W-load coordinates (64kk x 32 float4 tile, 8 loads/thread)
    int kk_p[8], n4_p[8];
#pragma unroll
    for (int j = 0; j < 8; ++j) {
        int idx = tid + j * 256;
        kk_p[j] = idx >> 5;           // 0..63
        n4_p[j] = idx & 31;           // 0..31
    }

    for (int nc = 0; nc < 4; ++nc) {
        const int N0  = nc * 128;
        const int N04 = N0 >> 2;

        // initial W ktile -> buf 0
        {
            float4* dst = reinterpret_cast<float4*>(Wt);
#pragma unroll
            for (int j = 0; j < 8; ++j)
                dst[kk_p[j] * 32 + n4_p[j]] =
                    Wg4[(size_t)kk_p[j] * 128 + N04 + n4_p[j]];
        }
        __syncthreads();   // first nc: also covers xT/bias/wc stores

        unsigned long long acc[2][8];
#pragma unroll
        for (int i = 0; i < 2; ++i)
#pragma unroll
            for (int j = 0; j < 8; ++j) acc[i][j] = 0ull;

        for (int t = 0; t < 8; ++t) {
            // prefetch next W ktile into registers
            float4 pre[8];
            if (t < 7) {
#pragma unroll
                for (int j = 0; j < 8; ++j)
                    pre[j] = Wg4[((size_t)(t + 1) * 64 + kk_p[j]) * 128 + N04 + n4_p[j]];
            }

            const float* Wb = Wt + (t & 1) * 8192;
#pragma unroll 8
            for (int kk = 0; kk < 64; ++kk) {
                const float* xr = xT + (t * 64 + kk) * XT_STRIDE + m0;
                unsigned long long a01 = *reinterpret_cast<const unsigned long long*>(xr);
                unsigned long long a23 = *reinterpret_cast<const unsigned long long*>(xr + 2);
                const float* wr = Wb + kk * 128 + tx * 4;
                float4 w0 = *reinterpret_cast<const float4*>(wr);
                float4 w1 = *reinterpret_cast<const float4*>(wr + 64);
                unsigned long long wd;
                wd = pack2(w0.x, w0.x); ffma2(acc[0][0], a01, wd); ffma2(acc[1][0], a23, wd);
                wd = pack2(w0.y, w0.y); ffma2(acc[0][1], a01, wd); ffma2(acc[1][1], a23, wd);
                wd = pack2(w0.z, w0.z); ffma2(acc[0][2], a01, wd); ffma2(acc[1][2], a23, wd);
                wd = pack2(w0.w, w0.w); ffma2(acc[0][3], a01, wd); ffma2(acc[1][3], a23, wd);
                wd = pack2(w1.x, w1.x); ffma2(acc[0][4], a01, wd); ffma2(acc[1][4], a23, wd);
                wd = pack2(w1.y, w1.y); ffma2(acc[0][5], a01, wd); ffma2(acc[1][5], a23, wd);
                wd = pack2(w1.z, w1.z); ffma2(acc[0][6], a01, wd); ffma2(acc[1][6], a23, wd);
                wd = pack2(w1.w, w1.w); ffma2(acc[0][7], a01, wd); ffma2(acc[1][7], a23, wd);
            }

            if (t < 7) {
                float4* dst = reinterpret_cast<float4*>(Wt + ((t + 1) & 1) * 8192);
#pragma unroll
                for (int j = 0; j < 8; ++j)
                    dst[kk_p[j] * 32 + n4_p[j]] = pre[j];
                __syncthreads();
            }
        }

        // epilogue: relu(p + bias) * Wc, accumulate per-m partial score
#pragma unroll
        for (int i = 0; i < 2; ++i) {
#pragma unroll
            for (int jj = 0; jj < 8; ++jj) {
                float plo, phi;
                unpack2(acc[i][jj], plo, phi);
                int n = N0 + ((jj < 4) ? (tx * 4 + jj) : (64 + tx * 4 + jj - 4));
                float bn = bias_s[n], wn = wc_s[n];
                float t0 = fmaxf(plo + bn, 0.0f) * wn;
                float t1 = fmaxf(phi + bn, 0.0f) * wn;
                if (i == 0) { s0 += t0; s1 += t1; }
                else        { s2 += t0; s3 += t1; }
            }
        }
        // no sync needed here: next nc writes buf0 (disjoint from buf1 readers)
        // and syncs before compute.
    }

    // cross-tx reduction of partial scores
    red[(m0 + 0) * 17 + tx] = s0;
    red[(m0 + 1) * 17 + tx] = s1;
    red[(m0 + 2) * 17 + tx] = s2;
    red[(m0 + 3) * 17 + tx] = s3;
    __syncthreads();
    if (tid < 64) {
        float sum = 0.f;
#pragma unroll
        for (int j = 0; j < 16; ++j) sum += red[tid * 17 + j];
        g_scores[b * LL + l0 + tid] = sum + bcomb[0];
    }
}

// =====================================================================
// Kernel C: softmax over L (per b) + weighted sum -> context[b][e]
// grid = (8 e-chunks, 64 b), 256 threads
// =====================================================================
__global__ __launch_bounds__(256)
void ctx_kernel(const float* __restrict__ x, float* __restrict__ out)
{
    __shared__ float sc[LL];
    __shared__ float redw[16];          // [0..7] max partials, [8..15] sum partials
    __shared__ float part[4][64];

    const int b   = blockIdx.y;
    const int e0  = blockIdx.x * 64;
    const int tid = threadIdx.x;
    const int lane = tid & 31, wid = tid >> 5;

    // load scores, local max
    float lmax = -1e30f;
#pragma unroll
    for (int i = tid; i < LL; i += 256) {
        float v = g_scores[b * LL + i];
        sc[i] = v;
        lmax = fmaxf(lmax, v);
    }
#pragma unroll
    for (int off = 16; off > 0; off >>= 1)
        lmax = fmaxf(lmax, __shfl_xor_sync(0xffffffffu, lmax, off));
    if (lane == 0) redw[wid] = lmax;
    __syncthreads();
    float gmax = redw[0];
#pragma unroll
    for (int j = 1; j < 8; ++j) gmax = fmaxf(gmax, redw[j]);

    // exp + local sum
    float lsum = 0.f;
#pragma unroll
    for (int i = tid; i < LL; i += 256) {
        float e = __expf(sc[i] - gmax);
        sc[i] = e;
        lsum += e;
    }
#pragma unroll
    for (int off = 16; off > 0; off >>= 1)
        lsum += __shfl_xor_sync(0xffffffffu, lsum, off);
    if (lane == 0) redw[8 + wid] = lsum;
    __syncthreads();
    float gsum = 0.f;
#pragma unroll
    for (int j = 0; j < 8; ++j) gsum += redw[8 + j];
    const float inv = 1.0f / gsum;

    // weighted sum over L for this e-chunk
    const int el = tid & 63;
    const int lg = tid >> 6;            // 0..3
    const float* xp = x + (size_t)b * LL * ENC + e0 + el;
    float acc = 0.f;
#pragma unroll 8
    for (int l = lg; l < LL; l += 4)
        acc += sc[l] * xp[(size_t)l * ENC];

    part[lg][el] = acc;
    __syncthreads();
    if (tid < 64)
        out[b * ENC + e0 + tid] =
            (part[0][tid] + part[1][tid] + part[2][tid] + part[3][tid]) * inv;
}

// =====================================================================
extern "C" void kernel_launch(void* const* d_in, const int* in_sizes, int n_in,
                              void* d_out, int out_size)
{
    const float* x      = (const float*)d_in[0];
    const float* str    = (const float*)d_in[1];
    const float* cell   = (const float*)d_in[2];
    const float* W_enc  = (const float*)d_in[3];
    const float* b_enc  = (const float*)d_in[4];
    const float* W_str  = (const float*)d_in[5];
    const float* b_str  = (const float*)d_in[6];
    const float* W_cell = (const float*)d_in[7];
    const float* b_cell = (const float*)d_in[8];
    const float* W_comb = (const float*)d_in[9];
    const float* b_comb = (const float*)d_in[10];
    float* out = (float*)d_out;

    cudaFuncSetAttribute(scores_kernel,
                         cudaFuncAttributeMaxDynamicSharedMemorySize, SMEM_B_BYTES);

    bias_kernel<<<BB, 512>>>(str, cell, W_str, b_str, W_cell, b_cell, b_enc);
    scores_kernel<<<dim3(LL / 64, BB), 256, SMEM_B_BYTES>>>(x, W_enc, W_comb, b_comb);
    ctx_kernel<<<dim3(ENC / 64, BB), 256>>>(x, out);
}

// round 9
// speedup vs baseline: 2.1214x; 2.1214x over previous
#include <cuda_runtime.h>
#include <cuda_bf16.h>
#include <cstdint>

#define BB    64
#define LL    1024
#define ENC   512
#define ATTN  512
#define STRH  256
#define CELLH 512

// ------------------- device scratch (static; no allocs) -------------------
__device__ float g_bpart[8 * BB * ATTN];
__device__ float g_scores2[2 * BB * LL];
__device__ __align__(16) __nv_bfloat16 g_wt_hi[ATTN * ENC];  // WT[n][k] hi
__device__ __align__(16) __nv_bfloat16 g_wt_lo[ATTN * ENC];  // WT[n][k] lo

// ------------------- helpers -------------------
__device__ __forceinline__ uint32_t smem_u32(const void* p) {
    uint32_t a;
    asm("{ .reg .u64 t; cvta.to.shared.u64 t, %1; cvt.u32.u64 %0, t; }"
        : "=r"(a) : "l"(p));
    return a;
}
__device__ __forceinline__ void cp16(uint32_t dst, const void* src) {
    asm volatile("cp.async.ca.shared.global [%0], [%1], 16;"
                 :: "r"(dst), "l"(src));
}
__device__ __forceinline__ void cp_commit() {
    asm volatile("cp.async.commit_group;");
}
template <int N>
__device__ __forceinline__ void cp_wait() {
    asm volatile("cp.async.wait_group %0;" :: "n"(N));
}

// pack two fp32 -> bf16x2 (x in low half)
__device__ __forceinline__ uint32_t bf2(float x, float y) {
    uint32_t r;
    asm("cvt.rn.bf16x2.f32 %0, %1, %2;" : "=r"(r) : "f"(y), "f"(x));
    return r;
}
// split a float2 into hi-bf16x2 and lo-bf16x2 (residual)
__device__ __forceinline__ void split2(float2 p, uint32_t& h, uint32_t& l) {
    h = bf2(p.x, p.y);
    __nv_bfloat162 hb = *reinterpret_cast<__nv_bfloat162*>(&h);
    l = bf2(p.x - __bfloat162float(hb.x), p.y - __bfloat162float(hb.y));
}

__device__ __forceinline__ void mma16816(float* d, const uint32_t* a,
                                         uint32_t b0, uint32_t b1) {
    asm volatile(
        "mma.sync.aligned.m16n8k16.row.col.f32.bf16.bf16.f32 "
        "{%0,%1,%2,%3}, {%4,%5,%6,%7}, {%8,%9}, {%0,%1,%2,%3};"
        : "+f"(d[0]), "+f"(d[1]), "+f"(d[2]), "+f"(d[3])
        : "r"(a[0]), "r"(a[1]), "r"(a[2]), "r"(a[3]), "r"(b0), "r"(b1));
}

// ===================== Kernel 1: W_enc -> WT hi/lo bf16 =====================
__global__ void convw_kernel(const float* __restrict__ W)
{
    __shared__ float t[32][33];
    const int n0 = blockIdx.x * 32, k0 = blockIdx.y * 32;
    const int tx = threadIdx.x, ty = threadIdx.y;
    t[ty][tx] = W[(k0 + ty) * ATTN + n0 + tx];
    __syncthreads();
    float v = t[tx][ty];                  // = W[k0+tx][n0+ty]
    __nv_bfloat16 h = __float2bfloat16(v);
    __nv_bfloat16 l = __float2bfloat16(v - __bfloat162float(h));
    g_wt_hi[(n0 + ty) * ENC + k0 + tx] = h;
    g_wt_lo[(n0 + ty) * ENC + k0 + tx] = l;
}

// ============ Kernel 2: bias split-K partials (deterministic) ============
__global__ __launch_bounds__(256)
void bias_gemm_kernel(const float* __restrict__ str, const float* __restrict__ cell,
                      const float* __restrict__ Wstr, const float* __restrict__ Wcell)
{
    __shared__ float Hs[96 * 65];
    const int ac = blockIdx.x & 7, es = blockIdx.x >> 3;
    const int a0 = ac * 64, e0 = es * 96;
    const int tid = threadIdx.x;

    for (int idx = tid; idx < 96 * 64; idx += 256) {
        int bb = idx / 96, el = idx - bb * 96;
        int e = e0 + el;
        Hs[el * 65 + bb] = (e < STRH) ? str[bb * STRH + e]
                                      : cell[bb * CELLH + (e - STRH)];
    }
    __syncthreads();

    const int ty = tid >> 4, tx = tid & 15;
    const int b0 = ty * 4, al = a0 + tx * 4;
    float acc[4][4];
#pragma unroll
    for (int i = 0; i < 4; ++i)
#pragma unroll
        for (int j = 0; j < 4; ++j) acc[i][j] = 0.f;

#pragma unroll 4
    for (int el = 0; el < 96; ++el) {
        int e = e0 + el;
        const float* wr = (e < STRH) ? (Wstr + e * ATTN) : (Wcell + (e - STRH) * ATTN);
        float w0 = wr[al], w1 = wr[al + 1], w2 = wr[al + 2], w3 = wr[al + 3];
#pragma unroll
        for (int i = 0; i < 4; ++i) {
            float h = Hs[el * 65 + b0 + i];
            acc[i][0] += h * w0; acc[i][1] += h * w1;
            acc[i][2] += h * w2; acc[i][3] += h * w3;
        }
    }
#pragma unroll
    for (int i = 0; i < 4; ++i)
#pragma unroll
        for (int j = 0; j < 4; ++j)
            g_bpart[(es * BB + b0 + i) * ATTN + al + j] = acc[i][j];
}

// ===================== Kernel 3: scores via HMMA (mma.sync) =====================
// grid (8 Ltiles, 64 b, 2 Nhalves), 512 threads (16 warps, 4x4 warp grid).
// Block tile M=128, N=256, K=512 in 8 chunks of 64. Warp tile 32x64.
// A: fp32 in smem (cp.async), bf16 hi/lo split built in registers.
// B: bf16 hi/lo (prepass) via cp.async.
// smem byte layout:
#define A_STRIDE  68                        // fp32 elems per row (padded)
#define A_BUF_B   (128 * A_STRIDE * 4)      // 34816
#define B_STRIDE  72                        // bf16 elems per row (padded)
#define B_SPLIT_B (256 * B_STRIDE * 2)      // 36864
#define B_BASE    (2 * A_BUF_B)             // 69632
#define BIAS_OFF  (B_BASE + 4 * B_SPLIT_B)  // 217088
#define WC_OFF    (BIAS_OFF + 1024)         // 218112
#define RED_OFF   (WC_OFF + 1024)           // 219136
#define S_TOTAL   (RED_OFF + 2048)          // 221184

__global__ __launch_bounds__(512, 1)
void scores_hmma_kernel(const float* __restrict__ x, const float* __restrict__ Wc,
                        const float* __restrict__ benc, const float* __restrict__ bstr,
                        const float* __restrict__ bcell)
{
    extern __shared__ char sm[];
    const uint32_t sb = smem_u32(sm);
    float* aF = (float*)sm;                                   // [2][128][68] fp32
    const __nv_bfloat16* btAll = (const __nv_bfloat16*)(sm + B_BASE);
    float* bias_s = (float*)(sm + BIAS_OFF);
    float* wc_s   = (float*)(sm + WC_OFF);
    float* red    = (float*)(sm + RED_OFF);                   // [128][4]

    const int tid = threadIdx.x;
    const int wid = tid >> 5, lane = tid & 31;
    const int g = lane >> 2, t = lane & 3;
    const int wm = wid >> 2, wn = wid & 3;
    const int b = blockIdx.y, l0 = blockIdx.x * 128, n0 = blockIdx.z * 256;

    // bias + wc into smem (folds split-K partials; b_comb dropped)
    if (tid < 256) {
        int a = n0 + tid;
        float bv = benc[a] + bstr[a] + bcell[a];
#pragma unroll
        for (int es = 0; es < 8; ++es)
            bv += g_bpart[(es * BB + b) * ATTN + a];
        bias_s[tid] = bv;
        wc_s[tid]   = Wc[a];
    }

    // per-thread staging coordinates
    const int arow = tid >> 4, aq = tid & 15;   // + it*512 stride
    const int brow = tid >> 3, bq = tid & 7;
    const float* xbase = x + ((size_t)(b * LL + l0)) * ENC;

    // stage(chunk c) into buffer c&1
#define STAGE(c) do { \
    uint32_t abuf = sb + (uint32_t)((c) & 1) * A_BUF_B; \
    uint32_t bbuf = sb + B_BASE + (uint32_t)((c) & 1) * (2 * B_SPLIT_B); \
    _Pragma("unroll") \
    for (int it = 0; it < 4; ++it) { \
        int row = arow + it * 32; \
        cp16(abuf + (uint32_t)row * (A_STRIDE * 4) + aq * 16, \
             xbase + (size_t)row * ENC + (c) * 64 + aq * 4); \
    } \
    _Pragma("unroll") \
    for (int it = 0; it < 4; ++it) { \
        int row = brow + it * 64; \
        uint32_t doff = (uint32_t)row * (B_STRIDE * 2) + bq * 16; \
        size_t soff = (size_t)(n0 + row) * ENC + (c) * 64 + bq * 8; \
        cp16(bbuf + doff, g_wt_hi + soff); \
        cp16(bbuf + B_SPLIT_B + doff, g_wt_lo + soff); \
    } \
} while (0)

    STAGE(0);
    cp_commit();

    float acc[2][8][4];
#pragma unroll
    for (int i = 0; i < 2; ++i)
#pragma unroll
        for (int j = 0; j < 8; ++j)
#pragma unroll
            for (int k = 0; k < 4; ++k) acc[i][j][k] = 0.f;

    for (int kc = 0; kc < 8; ++kc) {
        if (kc < 7) { STAGE(kc + 1); cp_commit(); cp_wait<1>(); }
        else        { cp_wait<0>(); }
        __syncthreads();

        const int cur = kc & 1;
        const float* aB = aF + cur * (128 * A_STRIDE);
        const __nv_bfloat16* bH = btAll + (size_t)cur * (2 * 256 * B_STRIDE);
        const __nv_bfloat16* bL = bH + 256 * B_STRIDE;

#pragma unroll
        for (int ks = 0; ks < 4; ++ks) {
            const int k0 = ks * 16;
            uint32_t ah[2][4], al[2][4];
#pragma unroll
            for (int mt = 0; mt < 2; ++mt) {
                const float* ar = aB + (wm * 32 + mt * 16 + g) * A_STRIDE + k0 + 2 * t;
                float2 p0 = *(const float2*)(ar);                    // row g,   k 2t
                float2 p1 = *(const float2*)(ar + 8 * A_STRIDE);     // row g+8, k 2t
                float2 p2 = *(const float2*)(ar + 8);                // row g,   k 2t+8
                float2 p3 = *(const float2*)(ar + 8 * A_STRIDE + 8); // row g+8, k 2t+8
                split2(p0, ah[mt][0], al[mt][0]);
                split2(p1, ah[mt][1], al[mt][1]);
                split2(p2, ah[mt][2], al[mt][2]);
                split2(p3, ah[mt][3], al[mt][3]);
            }
#pragma unroll
            for (int nt = 0; nt < 8; ++nt) {
                const int nrow = wn * 64 + nt * 8 + g;
                const __nv_bfloat16* brh = bH + nrow * B_STRIDE + k0 + 2 * t;
                const __nv_bfloat16* brl = bL + nrow * B_STRIDE + k0 + 2 * t;
                uint32_t bh0 = *(const uint32_t*)brh;
                uint32_t bh1 = *(const uint32_t*)(brh + 8);
                uint32_t bl0 = *(const uint32_t*)brl;
                uint32_t bl1 = *(const uint32_t*)(brl + 8);
                mma16816(acc[0][nt], ah[0], bh0, bh1);
                mma16816(acc[1][nt], ah[1], bh0, bh1);
                mma16816(acc[0][nt], al[0], bh0, bh1);
                mma16816(acc[1][nt], al[1], bh0, bh1);
                mma16816(acc[0][nt], ah[0], bl0, bl1);
                mma16816(acc[1][nt], ah[1], bl0, bl1);
            }
        }
        __syncthreads();
    }

    // epilogue: per-row partial of sum_n relu(d + bias[n]) * wc[n]
#pragma unroll
    for (int mt = 0; mt < 2; ++mt) {
        float pr0 = 0.f, pr1 = 0.f;
#pragma unroll
        for (int nt = 0; nt < 8; ++nt) {
            int c = wn * 64 + nt * 8 + 2 * t;
            float b0v = bias_s[c], b1v = bias_s[c + 1];
            float w0v = wc_s[c],   w1v = wc_s[c + 1];
            pr0 += fmaxf(acc[mt][nt][0] + b0v, 0.f) * w0v
                 + fmaxf(acc[mt][nt][1] + b1v, 0.f) * w1v;
            pr1 += fmaxf(acc[mt][nt][2] + b0v, 0.f) * w0v
                 + fmaxf(acc[mt][nt][3] + b1v, 0.f) * w1v;
        }
        pr0 += __shfl_xor_sync(0xffffffffu, pr0, 1);
        pr0 += __shfl_xor_sync(0xffffffffu, pr0, 2);
        pr1 += __shfl_xor_sync(0xffffffffu, pr1, 1);
        pr1 += __shfl_xor_sync(0xffffffffu, pr1, 2);
        if (t == 0) {
            int row = wm * 32 + mt * 16 + g;
            red[row * 4 + wn]       = pr0;
            red[(row + 8) * 4 + wn] = pr1;
        }
    }
    __syncthreads();
    if (tid < 128) {
        float s = red[tid * 4] + red[tid * 4 + 1] + red[tid * 4 + 2] + red[tid * 4 + 3];
        g_scores2[blockIdx.z * (BB * LL) + b * LL + l0 + tid] = s;
    }
#undef STAGE
}

// ============ Kernel 4: softmax over L + weighted sum ============
__global__ __launch_bounds__(256)
void ctx_kernel(const float* __restrict__ x, float* __restrict__ out)
{
    __shared__ float sc[LL];
    __shared__ float redw[16];
    __shared__ float part[4][64];

    const int b = blockIdx.y, e0 = blockIdx.x * 64;
    const int tid = threadIdx.x, lane = tid & 31, wid = tid >> 5;

    float lmax = -1e30f;
#pragma unroll
    for (int i = tid; i < LL; i += 256) {
        float v = g_scores2[b * LL + i] + g_scores2[BB * LL + b * LL + i];
        sc[i] = v;
        lmax = fmaxf(lmax, v);
    }
#pragma unroll
    for (int off = 16; off > 0; off >>= 1)
        lmax = fmaxf(lmax, __shfl_xor_sync(0xffffffffu, lmax, off));
    if (lane == 0) redw[wid] = lmax;
    __syncthreads();
    float gmax = redw[0];
#pragma unroll
    for (int j = 1; j < 8; ++j) gmax = fmaxf(gmax, redw[j]);

    float lsum = 0.f;
#pragma unroll
    for (int i = tid; i < LL; i += 256) {
        float e = __expf(sc[i] - gmax);
        sc[i] = e;
        lsum += e;
    }
#pragma unroll
    for (int off = 16; off > 0; off >>= 1)
        lsum += __shfl_xor_sync(0xffffffffu, lsum, off);
    if (lane == 0) redw[8 + wid] = lsum;
    __syncthreads();
    float gsum = 0.f;
#pragma unroll
    for (int j = 0; j < 8; ++j) gsum += redw[8 + j];
    const float inv = 1.0f / gsum;

    const int el = tid & 63, lg = tid >> 6;
    const float* xp = x + (size_t)b * LL * ENC + e0 + el;
    float acc = 0.f;
#pragma unroll 8
    for (int l = lg; l < LL; l += 4)
        acc += sc[l] * xp[(size_t)l * ENC];
    part[lg][el] = acc;
    __syncthreads();
    if (tid < 64)
        out[b * ENC + e0 + tid] =
            (part[0][tid] + part[1][tid] + part[2][tid] + part[3][tid]) * inv;
}

// =====================================================================
extern "C" void kernel_launch(void* const* d_in, const int* in_sizes, int n_in,
                              void* d_out, int out_size)
{
    const float* x      = (const float*)d_in[0];
    const float* str    = (const float*)d_in[1];
    const float* cell   = (const float*)d_in[2];
    const float* W_enc  = (const float*)d_in[3];
    const float* b_enc  = (const float*)d_in[4];
    const float* W_str  = (const float*)d_in[5];
    const float* b_str  = (const float*)d_in[6];
    const float* W_cell = (const float*)d_in[7];
    const float* b_cell = (const float*)d_in[8];
    const float* W_comb = (const float*)d_in[9];
    float* out = (float*)d_out;

    cudaFuncSetAttribute(scores_hmma_kernel,
                         cudaFuncAttributeMaxDynamicSharedMemorySize, S_TOTAL);

    convw_kernel<<<dim3(16, 16), dim3(32, 32)>>>(W_enc);
    bias_gemm_kernel<<<64, 256>>>(str, cell, W_str, W_cell);
    scores_hmma_kernel<<<dim3(8, BB, 2), 512, S_TOTAL>>>(x, W_comb, b_enc, b_str, b_cell);
    ctx_kernel<<<dim3(8, BB), 256>>>(x, out);
}

// round 11
// speedup vs baseline: 4.0333x; 1.9013x over previous
#include <cuda_runtime.h>
#include <cuda_fp16.h>
#include <cstdint>

#define BB    64
#define LL    1024
#define ENC   512
#define ATTN  512
#define STRH  256
#define CELLH 512

// ------------------- device scratch (static; no allocs) -------------------
__device__ float g_bpart[8 * BB * ATTN];
__device__ float g_scores2[2 * BB * LL];
__device__ __align__(16) __half g_wt16[ATTN * ENC];          // W^T fp16
__device__ __align__(16) __half g_x16[(size_t)BB * LL * ENC]; // x fp16

// ------------------- helpers -------------------
__device__ __forceinline__ uint32_t smem_u32(const void* p) {
    uint32_t a;
    asm("{ .reg .u64 t; cvta.to.shared.u64 t, %1; cvt.u32.u64 %0, t; }"
        : "=r"(a) : "l"(p));
    return a;
}
__device__ __forceinline__ void cp16(uint32_t dst, const void* src) {
    asm volatile("cp.async.ca.shared.global [%0], [%1], 16;"
                 :: "r"(dst), "l"(src));
}
__device__ __forceinline__ void cp_commit() {
    asm volatile("cp.async.commit_group;");
}
template <int N>
__device__ __forceinline__ void cp_wait() {
    asm volatile("cp.async.wait_group %0;" :: "n"(N));
}
__device__ __forceinline__ void ldm_x4(uint32_t* r, uint32_t addr) {
    asm volatile("ldmatrix.sync.aligned.m8n8.x4.shared.b16 {%0,%1,%2,%3}, [%4];"
                 : "=r"(r[0]), "=r"(r[1]), "=r"(r[2]), "=r"(r[3]) : "r"(addr));
}
__device__ __forceinline__ void mma16816(float* d, const uint32_t* a,
                                         uint32_t b0, uint32_t b1) {
    asm volatile(
        "mma.sync.aligned.m16n8k16.row.col.f32.f16.f16.f32 "
        "{%0,%1,%2,%3}, {%4,%5,%6,%7}, {%8,%9}, {%0,%1,%2,%3};"
        : "+f"(d[0]), "+f"(d[1]), "+f"(d[2]), "+f"(d[3])
        : "r"(a[0]), "r"(a[1]), "r"(a[2]), "r"(a[3]), "r"(b0), "r"(b1));
}

// ===================== Kernel 0: x -> fp16 =====================
__global__ __launch_bounds__(256)
void convx_kernel(const float* __restrict__ x)
{
    const size_t total4 = (size_t)BB * LL * ENC / 4;     // float4 count
    const float4* in = (const float4*)x;
    uint2* out = (uint2*)g_x16;
    size_t stride = (size_t)gridDim.x * blockDim.x;
    for (size_t i = (size_t)blockIdx.x * blockDim.x + threadIdx.x;
         i < total4; i += stride) {
        float4 v = in[i];
        __half2 h0 = __floats2half2_rn(v.x, v.y);
        __half2 h1 = __floats2half2_rn(v.z, v.w);
        uint2 o;
        o.x = *reinterpret_cast<uint32_t*>(&h0);
        o.y = *reinterpret_cast<uint32_t*>(&h1);
        out[i] = o;
    }
}

// ===================== Kernel 1: W_enc -> W^T fp16 =====================
__global__ void convw_kernel(const float* __restrict__ W)
{
    __shared__ float t[32][33];
    const int n0 = blockIdx.x * 32, k0 = blockIdx.y * 32;
    const int tx = threadIdx.x, ty = threadIdx.y;
    t[ty][tx] = W[(k0 + ty) * ATTN + n0 + tx];
    __syncthreads();
    g_wt16[(n0 + ty) * ENC + k0 + tx] = __float2half_rn(t[tx][ty]);
}

// ============ Kernel 2: bias split-K partials (deterministic) ============
__global__ __launch_bounds__(256)
void bias_gemm_kernel(const float* __restrict__ str, const float* __restrict__ cell,
                      const float* __restrict__ Wstr, const float* __restrict__ Wcell)
{
    __shared__ float Hs[96 * 65];
    const int ac = blockIdx.x & 7, es = blockIdx.x >> 3;
    const int a0 = ac * 64, e0 = es * 96;
    const int tid = threadIdx.x;

    for (int idx = tid; idx < 96 * 64; idx += 256) {
        int bb = idx / 96, el = idx - bb * 96;
        int e = e0 + el;
        Hs[el * 65 + bb] = (e < STRH) ? str[bb * STRH + e]
                                      : cell[bb * CELLH + (e - STRH)];
    }
    __syncthreads();

    const int ty = tid >> 4, tx = tid & 15;
    const int b0 = ty * 4, al = a0 + tx * 4;
    float acc[4][4];
#pragma unroll
    for (int i = 0; i < 4; ++i)
#pragma unroll
        for (int j = 0; j < 4; ++j) acc[i][j] = 0.f;

#pragma unroll 4
    for (int el = 0; el < 96; ++el) {
        int e = e0 + el;
        const float* wr = (e < STRH) ? (Wstr + e * ATTN) : (Wcell + (e - STRH) * ATTN);
        float w0 = wr[al], w1 = wr[al + 1], w2 = wr[al + 2], w3 = wr[al + 3];
#pragma unroll
        for (int i = 0; i < 4; ++i) {
            float h = Hs[el * 65 + b0 + i];
            acc[i][0] += h * w0; acc[i][1] += h * w1;
            acc[i][2] += h * w2; acc[i][3] += h * w3;
        }
    }
#pragma unroll
    for (int i = 0; i < 4; ++i)
#pragma unroll
        for (int j = 0; j < 4; ++j)
            g_bpart[(es * BB + b0 + i) * ATTN + al + j] = acc[i][j];
}

// ===================== Kernel 3: scores via fp16 HMMA =====================
// grid (8 Ltiles, 64 b, 2 Nhalves), 512 threads (16 warps, 4x4 warp grid).
// Block tile M=128, N=256, K=512 in 8 chunks of 64. Warp tile 32x64.
// A and B both fp16 in smem (cp.async), fragments via ldmatrix.
#define RSTRIDE   72                          // halfs per smem row (padded)
#define RBYTES    (RSTRIDE * 2)               // 144
#define A_BUF_B   (128 * RBYTES)              // 18432
#define B_OFF     (2 * A_BUF_B)               // 36864
#define B_BUF_B   (256 * RBYTES)              // 36864
#define BIAS_OFF  (B_OFF + 2 * B_BUF_B)       // 110592
#define WC_OFF    (BIAS_OFF + 1024)           // 111616
#define RED_OFF   (WC_OFF + 1024)             // 112640
#define S_TOTAL   (RED_OFF + 2048)            // 114688

__global__ __launch_bounds__(512, 1)
void scores_hmma_kernel(const float* __restrict__ Wc,
                        const float* __restrict__ benc, const float* __restrict__ bstr,
                        const float* __restrict__ bcell)
{
    extern __shared__ char sm[];
    const uint32_t sb = smem_u32(sm);
    float* bias_s = (float*)(sm + BIAS_OFF);
    float* wc_s   = (float*)(sm + WC_OFF);
    float* red    = (float*)(sm + RED_OFF);                   // [128][4]

    const int tid = threadIdx.x;
    const int wid = tid >> 5, lane = tid & 31;
    const int g = lane >> 2, t = lane & 3;
    const int wm = wid >> 2, wn = wid & 3;
    const int b = blockIdx.y, l0 = blockIdx.x * 128, n0 = blockIdx.z * 256;

    // bias + wc into smem (folds split-K partials; b_comb dropped)
    if (tid < 256) {
        int a = n0 + tid;
        float bv = benc[a] + bstr[a] + bcell[a];
#pragma unroll
        for (int es = 0; es < 8; ++es)
            bv += g_bpart[(es * BB + b) * ATTN + a];
        bias_s[tid] = bv;
        wc_s[tid]   = Wc[a];
    }

    const __half* xbase = g_x16 + ((size_t)(b * LL + l0)) * ENC;
    const __half* bbase = g_wt16 + (size_t)n0 * ENC;
    const int ar = tid >> 3, aq = tid & 7;     // staging coords

    // stage chunk c into buffer c&1
#define STAGE(c) do { \
    uint32_t abuf = sb + (uint32_t)((c) & 1) * A_BUF_B; \
    uint32_t bbuf = sb + B_OFF + (uint32_t)((c) & 1) * B_BUF_B; \
    _Pragma("unroll") \
    for (int it = 0; it < 2; ++it) { \
        int row = ar + it * 64; \
        cp16(abuf + (uint32_t)row * RBYTES + aq * 16, \
             xbase + (size_t)row * ENC + (c) * 64 + aq * 8); \
    } \
    _Pragma("unroll") \
    for (int it = 0; it < 4; ++it) { \
        int row = ar + it * 64; \
        cp16(bbuf + (uint32_t)row * RBYTES + aq * 16, \
             bbase + (size_t)row * ENC + (c) * 64 + aq * 8); \
    } \
} while (0)

    STAGE(0);
    cp_commit();

    float acc[2][8][4];
#pragma unroll
    for (int i = 0; i < 2; ++i)
#pragma unroll
        for (int j = 0; j < 8; ++j)
#pragma unroll
            for (int k = 0; k < 4; ++k) acc[i][j][k] = 0.f;

    // per-lane ldmatrix address components
    const int a_row = (lane & 15);             // + wm*32 + mt*16
    const int a_kof = (lane >> 4) * 8;         // + ks*16
    const int b_row = ((lane >> 4) << 3) + (lane & 7);   // + wn*64 + p*16
    const int b_kof = ((lane >> 3) & 1) * 8;   // + ks*16

    for (int kc = 0; kc < 8; ++kc) {
        if (kc < 7) { STAGE(kc + 1); cp_commit(); cp_wait<1>(); }
        else        { cp_wait<0>(); }
        __syncthreads();

        const uint32_t abuf = sb + (uint32_t)(kc & 1) * A_BUF_B;
        const uint32_t bbuf = sb + B_OFF + (uint32_t)(kc & 1) * B_BUF_B;

#pragma unroll
        for (int ks = 0; ks < 4; ++ks) {
            const int k0 = ks * 16;
            uint32_t af[2][4];
#pragma unroll
            for (int mt = 0; mt < 2; ++mt)
                ldm_x4(af[mt], abuf + (uint32_t)(wm * 32 + mt * 16 + a_row) * RBYTES
                                    + (uint32_t)(k0 + a_kof) * 2);
            uint32_t bf[4][4];
#pragma unroll
            for (int p = 0; p < 4; ++p)
                ldm_x4(bf[p], bbuf + (uint32_t)(wn * 64 + p * 16 + b_row) * RBYTES
                                   + (uint32_t)(k0 + b_kof) * 2);
#pragma unroll
            for (int mt = 0; mt < 2; ++mt)
#pragma unroll
                for (int nt = 0; nt < 8; ++nt)
                    mma16816(acc[mt][nt], af[mt],
                             bf[nt >> 1][(nt & 1) * 2], bf[nt >> 1][(nt & 1) * 2 + 1]);
        }
        __syncthreads();
    }

    // epilogue: per-row partial of sum_n relu(d + bias[n]) * wc[n]
#pragma unroll
    for (int mt = 0; mt < 2; ++mt) {
        float pr0 = 0.f, pr1 = 0.f;
#pragma unroll
        for (int nt = 0; nt < 8; ++nt) {
            int c = wn * 64 + nt * 8 + 2 * t;
            float b0v = bias_s[c], b1v = bias_s[c + 1];
            float w0v = wc_s[c],   w1v = wc_s[c + 1];
            pr0 += fmaxf(acc[mt][nt][0] + b0v, 0.f) * w0v
                 + fmaxf(acc[mt][nt][1] + b1v, 0.f) * w1v;
            pr1 += fmaxf(acc[mt][nt][2] + b0v, 0.f) * w0v
                 + fmaxf(acc[mt][nt][3] + b1v, 0.f) * w1v;
        }
        pr0 += __shfl_xor_sync(0xffffffffu, pr0, 1);
        pr0 += __shfl_xor_sync(0xffffffffu, pr0, 2);
        pr1 += __shfl_xor_sync(0xffffffffu, pr1, 1);
        pr1 += __shfl_xor_sync(0xffffffffu, pr1, 2);
        if (t == 0) {
            int row = wm * 32 + mt * 16 + g;
            red[row * 4 + wn]       = pr0;
            red[(row + 8) * 4 + wn] = pr1;
        }
    }
    __syncthreads();
    if (tid < 128) {
        float s = red[tid * 4] + red[tid * 4 + 1] + red[tid * 4 + 2] + red[tid * 4 + 3];
        g_scores2[blockIdx.z * (BB * LL) + b * LL + l0 + tid] = s;
    }
#undef STAGE
}

// ============ Kernel 4: softmax over L + weighted sum (fp16 x) ============
// grid (4 e-chunks of 128, 64 b), 256 threads
__global__ __launch_bounds__(256)
void ctx_kernel(float* __restrict__ out)
{
    __shared__ float sc[LL];
    __shared__ float redw[16];
    __shared__ float2 part2[4][64];

    const int b = blockIdx.y, e0 = blockIdx.x * 128;
    const int tid = threadIdx.x, lane = tid & 31, wid = tid >> 5;

    float lmax = -1e30f;
#pragma unroll
    for (int i = tid; i < LL; i += 256) {
        float v = g_scores2[b * LL + i] + g_scores2[BB * LL + b * LL + i];
        sc[i] = v;
        lmax = fmaxf(lmax, v);
    }
#pragma unroll
    for (int off = 16; off > 0; off >>= 1)
        lmax = fmaxf(lmax, __shfl_xor_sync(0xffffffffu, lmax, off));
    if (lane == 0) redw[wid] = lmax;
    __syncthreads();
    float gmax = redw[0];
#pragma unroll
    for (int j = 1; j < 8; ++j) gmax = fmaxf(gmax, redw[j]);

    float lsum = 0.f;
#pragma unroll
    for (int i = tid; i < LL; i += 256) {
        float e = __expf(sc[i] - gmax);
        sc[i] = e;
        lsum += e;
    }
#pragma unroll
    for (int off = 16; off > 0; off >>= 1)
        lsum += __shfl_xor_sync(0xffffffffu, lsum, off);
    if (lane == 0) redw[8 + wid] = lsum;
    __syncthreads();
    float gsum = 0.f;
#pragma unroll
    for (int j = 0; j < 8; ++j) gsum += redw[8 + j];
    const float inv = 1.0f / gsum;

    const int el2 = tid & 63, lg = tid >> 6;
    const __half2* xp = (const __half2*)(g_x16 + (size_t)b * LL * ENC + e0) + el2;
    float ax = 0.f, ay = 0.f;
#pragma unroll 8
    for (int l = lg; l < LL; l += 4) {
        float2 f = __half22float2(xp[(size_t)l * (ENC / 2)]);
        float w = sc[l];
        ax += w * f.x;
        ay += w * f.y;
    }
    part2[lg][el2] = make_float2(ax, ay);
    __syncthreads();
    if (tid < 64) {
        float2 s = part2[0][tid];
        s.x += part2[1][tid].x + part2[2][tid].x + part2[3][tid].x;
        s.y += part2[1][tid].y + part2[2][tid].y + part2[3][tid].y;
        float2* o = (float2*)(out + b * ENC + e0) + tid;
        *o = make_float2(s.x * inv, s.y * inv);
    }
}

// =====================================================================
extern "C" void kernel_launch(void* const* d_in, const int* in_sizes, int n_in,
                              void* d_out, int out_size)
{
    const float* x      = (const float*)d_in[0];
    const float* str    = (const float*)d_in[1];
    const float* cell   = (const float*)d_in[2];
    const float* W_enc  = (const float*)d_in[3];
    const float* b_enc  = (const float*)d_in[4];
    const float* W_str  = (const float*)d_in[5];
    const float* b_str  = (const float*)d_in[6];
    const float* W_cell = (const float*)d_in[7];
    const float* b_cell = (const float*)d_in[8];
    const float* W_comb = (const float*)d_in[9];
    float* out = (float*)d_out;

    cudaFuncSetAttribute(scores_hmma_kernel,
                         cudaFuncAttributeMaxDynamicSharedMemorySize, S_TOTAL);

    convx_kernel<<<2048, 256>>>(x);
    convw_kernel<<<dim3(16, 16), dim3(32, 32)>>>(W_enc);
    bias_gemm_kernel<<<64, 256>>>(str, cell, W_str, W_cell);
    scores_hmma_kernel<<<dim3(8, BB, 2), 512, S_TOTAL>>>(W_comb, b_enc, b_str, b_cell);
    ctx_kernel<<<dim3(4, BB), 256>>>(out);
}

// round 15
// speedup vs baseline: 4.2421x; 1.0518x over previous
#include <cuda_runtime.h>
#include <cuda_fp16.h>
#include <cstdint>

#define BB    64
#define LL    1024
#define ENC   512
#define ATTN  512
#define STRH  256
#define CELLH 512

// ------------------- device scratch (static; no allocs) -------------------
__device__ float g_bpart[8 * BB * ATTN];
__device__ float g_scores2[2 * BB * LL];
__device__ __align__(16) __half g_wt16[ATTN * ENC];          // W^T fp16

// ------------------- helpers -------------------
__device__ __forceinline__ uint32_t smem_u32(const void* p) {
    uint32_t a;
    asm("{ .reg .u64 t; cvta.to.shared.u64 t, %1; cvt.u32.u64 %0, t; }"
        : "=r"(a) : "l"(p));
    return a;
}
__device__ __forceinline__ void cp16(uint32_t dst, const void* src) {
    asm volatile("cp.async.ca.shared.global [%0], [%1], 16;"
                 :: "r"(dst), "l"(src));
}
__device__ __forceinline__ void cp_commit() {
    asm volatile("cp.async.commit_group;");
}
template <int N>
__device__ __forceinline__ void cp_wait() {
    asm volatile("cp.async.wait_group %0;" :: "n"(N));
}
__device__ __forceinline__ void ldm_x4(uint32_t* r, uint32_t addr) {
    asm volatile("ldmatrix.sync.aligned.m8n8.x4.shared.b16 {%0,%1,%2,%3}, [%4];"
                 : "=r"(r[0]), "=r"(r[1]), "=r"(r[2]), "=r"(r[3]) : "r"(addr));
}
__device__ __forceinline__ void mma16816(float* d, const uint32_t* a,
                                         uint32_t b0, uint32_t b1) {
    asm volatile(
        "mma.sync.aligned.m16n8k16.row.col.f32.f16.f16.f32 "
        "{%0,%1,%2,%3}, {%4,%5,%6,%7}, {%8,%9}, {%0,%1,%2,%3};"
        : "+f"(d[0]), "+f"(d[1]), "+f"(d[2]), "+f"(d[3])
        : "r"(a[0]), "r"(a[1]), "r"(a[2]), "r"(a[3]), "r"(b0), "r"(b1));
}

// ===================== Kernel 1: W_enc -> W^T fp16 =====================
__global__ void convw_kernel(const float* __restrict__ W)
{
    __shared__ float t[32][33];
    const int n0 = blockIdx.x * 32, k0 = blockIdx.y * 32;
    const int tx = threadIdx.x, ty = threadIdx.y;
    t[ty][tx] = W[(k0 + ty) * ATTN + n0 + tx];
    __syncthreads();
    g_wt16[(n0 + ty) * ENC + k0 + tx] = __float2half_rn(t[tx][ty]);
}

// ============ Kernel 2: bias split-K partials (deterministic) ============
__global__ __launch_bounds__(256)
void bias_gemm_kernel(const float* __restrict__ str, const float* __restrict__ cell,
                      const float* __restrict__ Wstr, const float* __restrict__ Wcell)
{
    __shared__ float Hs[96 * 65];
    const int ac = blockIdx.x & 7, es = blockIdx.x >> 3;
    const int a0 = ac * 64, e0 = es * 96;
    const int tid = threadIdx.x;

    for (int idx = tid; idx < 96 * 64; idx += 256) {
        int bb = idx / 96, el = idx - bb * 96;
        int e = e0 + el;
        Hs[el * 65 + bb] = (e < STRH) ? str[bb * STRH + e]
                                      : cell[bb * CELLH + (e - STRH)];
    }
    __syncthreads();

    const int ty = tid >> 4, tx = tid & 15;
    const int b0 = ty * 4, al = a0 + tx * 4;
    float acc[4][4];
#pragma unroll
    for (int i = 0; i < 4; ++i)
#pragma unroll
        for (int j = 0; j < 4; ++j) acc[i][j] = 0.f;

#pragma unroll 4
    for (int el = 0; el < 96; ++el) {
        int e = e0 + el;
        const float* wr = (e < STRH) ? (Wstr + e * ATTN) : (Wcell + (e - STRH) * ATTN);
        float w0 = wr[al], w1 = wr[al + 1], w2 = wr[al + 2], w3 = wr[al + 3];
#pragma unroll
        for (int i = 0; i < 4; ++i) {
            float h = Hs[el * 65 + b0 + i];
            acc[i][0] += h * w0; acc[i][1] += h * w1;
            acc[i][2] += h * w2; acc[i][3] += h * w3;
        }
    }
#pragma unroll
    for (int i = 0; i < 4; ++i)
#pragma unroll
        for (int j = 0; j < 4; ++j)
            g_bpart[(es * BB + b0 + i) * ATTN + al + j] = acc[i][j];
}

// ===================== Kernel 3: scores via fp16 HMMA =====================
// grid (16 Ltiles, 64 b, 2 Nhalves), 256 threads (8 warps, 2m x 4n),
// 2 CTAs/SM. Block tile M=64, N=256, K=512 in 8 chunks of 64.
// Warp tile 32x64. A: fp32 global -> cvt fp16 -> STS (double buffer).
// B: fp16 W^T via cp.async (double buffer).
#define RSTRIDE   72                          // halfs per smem row (padded)
#define RBYTES    (RSTRIDE * 2)               // 144
#define A_BUF_B   (64 * RBYTES)               // 9216
#define B_OFF     (2 * A_BUF_B)               // 18432
#define B_BUF_B   (256 * RBYTES)              // 36864
#define BIAS_OFF  (B_OFF + 2 * B_BUF_B)       // 92160
#define WC_OFF    (BIAS_OFF + 1024)           // 93184
#define RED_OFF   (WC_OFF + 1024)             // 94208
#define S_TOTAL   (RED_OFF + 1024)            // 95232 (x2 CTAs = 186KB/SM)

__global__ __launch_bounds__(256, 2)
void scores_hmma_kernel(const float* __restrict__ x, const float* __restrict__ Wc,
                        const float* __restrict__ benc, const float* __restrict__ bstr,
                        const float* __restrict__ bcell)
{
    extern __shared__ char sm[];
    const uint32_t sb = smem_u32(sm);
    float* bias_s = (float*)(sm + BIAS_OFF);
    float* wc_s   = (float*)(sm + WC_OFF);
    float* red    = (float*)(sm + RED_OFF);                   // [64][4]

    const int tid = threadIdx.x;
    const int wid = tid >> 5, lane = tid & 31;
    const int g = lane >> 2, t = lane & 3;
    const int wm = wid >> 2, wn = wid & 3;                    // 2m x 4n
    const int b = blockIdx.y, l0 = blockIdx.x * 64, n0 = blockIdx.z * 256;

    // bias + wc into smem (folds split-K partials; b_comb dropped)
    {
        int a = n0 + tid;
        float bv = benc[a] + bstr[a] + bcell[a];
#pragma unroll
        for (int es = 0; es < 8; ++es)
            bv += g_bpart[(es * BB + b) * ATTN + a];
        bias_s[tid] = bv;
        wc_s[tid]   = Wc[a];
    }

    const float* xbase = x + ((size_t)(b * LL + l0)) * ENC;
    const __half* bbase = g_wt16 + (size_t)n0 * ENC;

    // A staging coords: 64 rows x 64 fp32 per chunk; 16 floats/thread
    const int a_r = tid >> 2;                  // 0..63
    const int a_c = (tid & 3) * 16;            // 0/16/32/48
    // B staging coords: 256 rows x 64 halfs; 8 x cp16 per thread
    const int b_r = tid >> 3, b_q = tid & 7;

    float4 pa[4];
#define LDG_A(c) do { \
    const float* ap = xbase + (size_t)a_r * ENC + (c) * 64 + a_c; \
    pa[0] = *(const float4*)(ap);      pa[1] = *(const float4*)(ap + 4); \
    pa[2] = *(const float4*)(ap + 8);  pa[3] = *(const float4*)(ap + 12); \
} while (0)
#define STS_A(c) do { \
    uint32_t abuf = sb + (uint32_t)((c) & 1) * A_BUF_B \
                  + (uint32_t)a_r * RBYTES + (uint32_t)a_c * 2; \
    _Pragma("unroll") \
    for (int i = 0; i < 4; ++i) { \
        __half2 h0 = __floats2half2_rn(pa[i].x, pa[i].y); \
        __half2 h1 = __floats2half2_rn(pa[i].z, pa[i].w); \
        uint2 o; \
        o.x = *reinterpret_cast<uint32_t*>(&h0); \
        o.y = *reinterpret_cast<uint32_t*>(&h1); \
        *(uint2*)((char*)sm + (abuf - sb) + i * 8) = o; \
    } \
} while (0)
#define STAGE_B(c) do { \
    uint32_t bbuf = sb + B_OFF + (uint32_t)((c) & 1) * B_BUF_B; \
    _Pragma("unroll") \
    for (int it = 0; it < 8; ++it) { \
        int row = b_r + it * 32; \
        cp16(bbuf + (uint32_t)row * RBYTES + b_q * 16, \
             bbase + (size_t)row * ENC + (c) * 64 + b_q * 8); \
    } \
} while (0)

    LDG_A(0);
    STAGE_B(0);
    cp_commit();

    float acc[2][8][4];
#pragma unroll
    for (int i = 0; i < 2; ++i)
#pragma unroll
        for (int j = 0; j < 8; ++j)
#pragma unroll
            for (int k = 0; k < 4; ++k) acc[i][j][k] = 0.f;

    // per-lane ldmatrix address components (identical mapping to R10)
    const int a_row = (lane & 15);
    const int a_kof = (lane >> 4) * 8;
    const int b_row = ((lane >> 4) << 3) + (lane & 7);
    const int b_kof = ((lane >> 3) & 1) * 8;

    for (int kc = 0; kc < 8; ++kc) {
        STS_A(kc);
        if (kc < 7) {
            LDG_A(kc + 1);
            STAGE_B(kc + 1);
            cp_commit();
            cp_wait<1>();
        } else {
            cp_wait<0>();
        }
        __syncthreads();

        const uint32_t abuf = sb + (uint32_t)(kc & 1) * A_BUF_B;
        const uint32_t bbuf = sb + B_OFF + (uint32_t)(kc & 1) * B_BUF_B;

#pragma unroll
        for (int ks = 0; ks < 4; ++ks) {
            const int k0 = ks * 16;
            uint32_t af[2][4];
#pragma unroll
            for (int mt = 0; mt < 2; ++mt)
                ldm_x4(af[mt], abuf + (uint32_t)(wm * 32 + mt * 16 + a_row) * RBYTES
                                    + (uint32_t)(k0 + a_kof) * 2);
            uint32_t bf[4][4];
#pragma unroll
            for (int p = 0; p < 4; ++p)
                ldm_x4(bf[p], bbuf + (uint32_t)(wn * 64 + p * 16 + b_row) * RBYTES
                                   + (uint32_t)(k0 + b_kof) * 2);
#pragma unroll
            for (int mt = 0; mt < 2; ++mt)
#pragma unroll
                for (int nt = 0; nt < 8; ++nt)
                    mma16816(acc[mt][nt], af[mt],
                             bf[nt >> 1][(nt & 1) * 2], bf[nt >> 1][(nt & 1) * 2 + 1]);
        }
        __syncthreads();
    }

    // epilogue: per-row partial of sum_n relu(d + bias[n]) * wc[n]
#pragma unroll
    for (int mt = 0; mt < 2; ++mt) {
        float pr0 = 0.f, pr1 = 0.f;
#pragma unroll
        for (int nt = 0; nt < 8; ++nt) {
            int c = wn * 64 + nt * 8 + 2 * t;
            float b0v = bias_s[c], b1v = bias_s[c + 1];
            float w0v = wc_s[c],   w1v = wc_s[c + 1];
            pr0 += fmaxf(acc[mt][nt][0] + b0v, 0.f) * w0v
                 + fmaxf(acc[mt][nt][1] + b1v, 0.f) * w1v;
            pr1 += fmaxf(acc[mt][nt][2] + b0v, 0.f) * w0v
                 + fmaxf(acc[mt][nt][3] + b1v, 0.f) * w1v;
        }
        pr0 += __shfl_xor_sync(0xffffffffu, pr0, 1);
        pr0 += __shfl_xor_sync(0xffffffffu, pr0, 2);
        pr1 += __shfl_xor_sync(0xffffffffu, pr1, 1);
        pr1 += __shfl_xor_sync(0xffffffffu, pr1, 2);
        if (t == 0) {
            int row = wm * 32 + mt * 16 + g;
            red[row * 4 + wn]       = pr0;
            red[(row + 8) * 4 + wn] = pr1;
        }
    }
    __syncthreads();
    if (tid < 64) {
        float s = red[tid * 4] + red[tid * 4 + 1] + red[tid * 4 + 2] + red[tid * 4 + 3];
        g_scores2[blockIdx.z * (BB * LL) + b * LL + l0 + tid] = s;
    }
#undef LDG_A
#undef STS_A
#undef STAGE_B
}

// ============ Kernel 4: softmax over L + weighted sum (fp32 x) ============
// grid (8 e-chunks of 64, 64 b), 256 threads
__global__ __launch_bounds__(256)
void ctx_kernel(const float* __restrict__ x, float* __restrict__ out)
{
    __shared__ float sc[LL];
    __shared__ float redw[16];
    __shared__ float part[4][64];

    const int b = blockIdx.y, e0 = blockIdx.x * 64;
    const int tid = threadIdx.x, lane = tid & 31, wid = tid >> 5;

    float lmax = -1e30f;
#pragma unroll
    for (int i = tid; i < LL; i += 256) {
        float v = g_scores2[b * LL + i] + g_scores2[BB * LL + b * LL + i];
        sc[i] = v;
        lmax = fmaxf(lmax, v);
    }
#pragma unroll
    for (int off = 16; off > 0; off >>= 1)
        lmax = fmaxf(lmax, __shfl_xor_sync(0xffffffffu, lmax, off));
    if (lane == 0) redw[wid] = lmax;
    __syncthreads();
    float gmax = redw[0];
#pragma unroll
    for (int j = 1; j < 8; ++j) gmax = fmaxf(gmax, redw[j]);

    float lsum = 0.f;
#pragma unroll
    for (int i = tid; i < LL; i += 256) {
        float e = __expf(sc[i] - gmax);
        sc[i] = e;
        lsum += e;
    }
#pragma unroll
    for (int off = 16; off > 0; off >>= 1)
        lsum += __shfl_xor_sync(0xffffffffu, lsum, off);
    if (lane == 0) redw[8 + wid] = lsum;
    __syncthreads();
    float gsum = 0.f;
#pragma unroll
    for (int j = 0; j < 8; ++j) gsum += redw[8 + j];
    const float inv = 1.0f / gsum;

    const int el = tid & 63, lg = tid >> 6;
    const float* xp = x + (size_t)b * LL * ENC + e0 + el;
    float acc = 0.f;
#pragma unroll 8
    for (int l = lg; l < LL; l += 4)
        acc += sc[l] * xp[(size_t)l * ENC];
    part[lg][el] = acc;
    __syncthreads();
    if (tid < 64)
        out[b * ENC + e0 + tid] =
            (part[0][tid] + part[1][tid] + part[2][tid] + part[3][tid]) * inv;
}

// =====================================================================
extern "C" void kernel_launch(void* const* d_in, const int* in_sizes, int n_in,
                              void* d_out, int out_size)
{
    const float* x      = (const float*)d_in[0];
    const float* str    = (const float*)d_in[1];
    const float* cell   = (const float*)d_in[2];
    const float* W_enc  = (const float*)d_in[3];
    const float* b_enc  = (const float*)d_in[4];
    const float* W_str  = (const float*)d_in[5];
    const float* b_str  = (const float*)d_in[6];
    const float* W_cell = (const float*)d_in[7];
    const float* b_cell = (const float*)d_in[8];
    const float* W_comb = (const float*)d_in[9];
    float* out = (float*)d_out;

    cudaFuncSetAttribute(scores_hmma_kernel,
                         cudaFuncAttributeMaxDynamicSharedMemorySize, S_TOTAL);

    convw_kernel<<<dim3(16, 16), dim3(32, 32)>>>(W_enc);
    bias_gemm_kernel<<<64, 256>>>(str, cell, W_str, W_cell);
    scores_hmma_kernel<<<dim3(16, BB, 2), 256, S_TOTAL>>>(x, W_comb, b_enc, b_str, b_cell);
    ctx_kernel<<<dim3(8, BB), 256>>>(x, out);
}

// round 16
// speedup vs baseline: 4.2677x; 1.0060x over previous
#include <cuda_runtime.h>
#include <cuda_fp16.h>
#include <cstdint>

#define BB    64
#define LL    1024
#define ENC   512
#define ATTN  512
#define STRH  256
#define CELLH 512

// ------------------- device scratch (static; no allocs) -------------------
__device__ float g_bpart[8 * BB * ATTN];
__device__ float g_scores2[2 * BB * LL];
__device__ __align__(16) __half g_wt16[ATTN * ENC];          // W^T fp16

// ------------------- helpers -------------------
__device__ __forceinline__ uint32_t smem_u32(const void* p) {
    uint32_t a;
    asm("{ .reg .u64 t; cvta.to.shared.u64 t, %1; cvt.u32.u64 %0, t; }"
        : "=r"(a) : "l"(p));
    return a;
}
__device__ __forceinline__ void cp16(uint32_t dst, const void* src) {
    asm volatile("cp.async.ca.shared.global [%0], [%1], 16;"
                 :: "r"(dst), "l"(src));
}
__device__ __forceinline__ void cp_commit() {
    asm volatile("cp.async.commit_group;");
}
template <int N>
__device__ __forceinline__ void cp_wait() {
    asm volatile("cp.async.wait_group %0;" :: "n"(N));
}
__device__ __forceinline__ void ldm_x4(uint32_t* r, uint32_t addr) {
    asm volatile("ldmatrix.sync.aligned.m8n8.x4.shared.b16 {%0,%1,%2,%3}, [%4];"
                 : "=r"(r[0]), "=r"(r[1]), "=r"(r[2]), "=r"(r[3]) : "r"(addr));
}
__device__ __forceinline__ void mma16816(float* d, const uint32_t* a,
                                         uint32_t b0, uint32_t b1) {
    asm volatile(
        "mma.sync.aligned.m16n8k16.row.col.f32.f16.f16.f32 "
        "{%0,%1,%2,%3}, {%4,%5,%6,%7}, {%8,%9}, {%0,%1,%2,%3};"
        : "+f"(d[0]), "+f"(d[1]), "+f"(d[2]), "+f"(d[3])
        : "r"(a[0]), "r"(a[1]), "r"(a[2]), "r"(a[3]), "r"(b0), "r"(b1));
}

// ====== Kernel 1 (merged prep): blocks 0..255 convw, 256..319 bias ======
__global__ __launch_bounds__(256)
void prep_kernel(const float* __restrict__ W,
                 const float* __restrict__ str, const float* __restrict__ cell,
                 const float* __restrict__ Wstr, const float* __restrict__ Wcell)
{
    __shared__ float sh[96 * 65];                 // 24960 floats max
    const int bid = blockIdx.x;
    const int tid = threadIdx.x;

    if (bid < 256) {
        // ---- convw: W_enc -> W^T fp16 (32x32 tile) ----
        float (*t)[33] = (float(*)[33])sh;
        const int n0 = (bid & 15) * 32, k0 = (bid >> 4) * 32;
#pragma unroll
        for (int j = 0; j < 4; ++j) {
            int i = tid + j * 256;
            int r = i >> 5, c = i & 31;
            t[r][c] = W[(k0 + r) * ATTN + n0 + c];
        }
        __syncthreads();
#pragma unroll
        for (int j = 0; j < 4; ++j) {
            int i = tid + j * 256;
            int r = i >> 5, c = i & 31;
            g_wt16[(n0 + r) * ENC + k0 + c] = __float2half_rn(t[c][r]);
        }
        return;
    }

    // ---- bias split-K partials (deterministic) ----
    const int blk = bid - 256;
    const int ac = blk & 7, es = blk >> 3;
    const int a0 = ac * 64, e0 = es * 96;

    for (int idx = tid; idx < 96 * 64; idx += 256) {
        int bb = idx / 96, el = idx - bb * 96;
        int e = e0 + el;
        sh[el * 65 + bb] = (e < STRH) ? str[bb * STRH + e]
                                      : cell[bb * CELLH + (e - STRH)];
    }
    __syncthreads();

    const int ty = tid >> 4, tx = tid & 15;
    const int b0 = ty * 4, al = a0 + tx * 4;
    float acc[4][4];
#pragma unroll
    for (int i = 0; i < 4; ++i)
#pragma unroll
        for (int j = 0; j < 4; ++j) acc[i][j] = 0.f;

#pragma unroll 4
    for (int el = 0; el < 96; ++el) {
        int e = e0 + el;
        const float* wr = (e < STRH) ? (Wstr + e * ATTN) : (Wcell + (e - STRH) * ATTN);
        float w0 = wr[al], w1 = wr[al + 1], w2 = wr[al + 2], w3 = wr[al + 3];
#pragma unroll
        for (int i = 0; i < 4; ++i) {
            float h = sh[el * 65 + b0 + i];
            acc[i][0] += h * w0; acc[i][1] += h * w1;
            acc[i][2] += h * w2; acc[i][3] += h * w3;
        }
    }
#pragma unroll
    for (int i = 0; i < 4; ++i)
#pragma unroll
        for (int j = 0; j < 4; ++j)
            g_bpart[(es * BB + b0 + i) * ATTN + al + j] = acc[i][j];
}

// ===================== Kernel 2: scores via fp16 HMMA =====================
// grid (8 Ltiles, 64 b, 2 Nhalves), 512 threads (16 warps, 4m x 4n).
// Block tile M=128, N=256, K=512 in 8 chunks of 64. Warp tile 32x64.
// THREE-stage pipeline, ONE __syncthreads per chunk.
// A: fp32 LDG -> cvt fp16 regs -> STS (staged 2 chunks ahead).
// B: fp16 W^T via cp.async (staged 2 chunks ahead).
#define RSTRIDE   72                          // halfs per smem row (padded)
#define RBYTES    (RSTRIDE * 2)               // 144
#define A_STG_B   (128 * RBYTES)              // 18432
#define B_OFF3    (3 * A_STG_B)               // 55296
#define B_STG_B   (256 * RBYTES)              // 36864
#define BIAS_OFF  (B_OFF3 + 3 * B_STG_B)      // 165888
#define WC_OFF    (BIAS_OFF + 1024)           // 166912
#define RED_OFF   (WC_OFF + 1024)             // 167936
#define S_TOTAL   (RED_OFF + 2048)            // 169984

__global__ __launch_bounds__(512, 1)
void scores_hmma_kernel(const float* __restrict__ x, const float* __restrict__ Wc,
                        const float* __restrict__ benc, const float* __restrict__ bstr,
                        const float* __restrict__ bcell)
{
    extern __shared__ char sm[];
    const uint32_t sb = smem_u32(sm);
    float* bias_s = (float*)(sm + BIAS_OFF);
    float* wc_s   = (float*)(sm + WC_OFF);
    float* red    = (float*)(sm + RED_OFF);                   // [128][4]

    const int tid = threadIdx.x;
    const int wid = tid >> 5, lane = tid & 31;
    const int g = lane >> 2, t = lane & 3;
    const int wm = wid >> 2, wn = wid & 3;                    // 4m x 4n
    const int b = blockIdx.y, l0 = blockIdx.x * 128, n0 = blockIdx.z * 256;

    // bias + wc into smem (folds split-K partials; b_comb dropped)
    if (tid < 256) {
        int a = n0 + tid;
        float bv = benc[a] + bstr[a] + bcell[a];
#pragma unroll
        for (int es = 0; es < 8; ++es)
            bv += g_bpart[(es * BB + b) * ATTN + a];
        bias_s[tid] = bv;
        wc_s[tid]   = Wc[a];
    }

    const float* xbase = x + ((size_t)(b * LL + l0)) * ENC;
    const __half* bbase = g_wt16 + (size_t)n0 * ENC;

    // A staging: 128 rows x 64 fp32/chunk, 16 floats per thread
    const int a_r = tid >> 2;                  // 0..127
    const int a_c = (tid & 3) * 16;            // 0/16/32/48
    // B staging: 256 rows x 64 halfs/chunk, 4 rows per thread
    const int b_r = tid >> 3, b_q = tid & 7;

    float4 pa[4];
#define LDG_A(c) do { \
    const float* ap = xbase + (size_t)a_r * ENC + (c) * 64 + a_c; \
    pa[0] = *(const float4*)(ap);      pa[1] = *(const float4*)(ap + 4); \
    pa[2] = *(const float4*)(ap + 8);  pa[3] = *(const float4*)(ap + 12); \
} while (0)
#define STS_A(stg) do { \
    char* ad = sm + (stg) * A_STG_B + (uint32_t)a_r * RBYTES + (uint32_t)a_c * 2; \
    _Pragma("unroll") \
    for (int i = 0; i < 4; ++i) { \
        __half2 h0 = __floats2half2_rn(pa[i].x, pa[i].y); \
        __half2 h1 = __floats2half2_rn(pa[i].z, pa[i].w); \
        uint2 o; \
        o.x = *reinterpret_cast<uint32_t*>(&h0); \
        o.y = *reinterpret_cast<uint32_t*>(&h1); \
        *(uint2*)(ad + i * 8) = o; \
    } \
} while (0)
#define STAGE_B(c, stg) do { \
    uint32_t bbuf = sb + B_OFF3 + (uint32_t)(stg) * B_STG_B; \
    _Pragma("unroll") \
    for (int it = 0; it < 4; ++it) { \
        int row = b_r + it * 64; \
        cp16(bbuf + (uint32_t)row * RBYTES + b_q * 16, \
             bbase + (size_t)row * ENC + (c) * 64 + b_q * 8); \
    } \
} while (0)

    // prologue: stage chunks 0,1; preload chunk 2 into regs
    LDG_A(0); STS_A(0);
    LDG_A(1); STS_A(1);
    LDG_A(2);
    STAGE_B(0, 0); cp_commit();
    STAGE_B(1, 1); cp_commit();

    float acc[2][8][4];
#pragma unroll
    for (int i = 0; i < 2; ++i)
#pragma unroll
        for (int j = 0; j < 8; ++j)
#pragma unroll
            for (int k = 0; k < 4; ++k) acc[i][j][k] = 0.f;

    // per-lane ldmatrix address components (proven mapping)
    const int a_row = (lane & 15);
    const int a_kof = (lane >> 4) * 8;
    const int b_row = ((lane >> 4) << 3) + (lane & 7);
    const int b_kof = ((lane >> 3) & 1) * 8;

    int st = 0;                                  // stage index = kc % 3
    for (int kc = 0; kc < 8; ++kc) {
        cp_wait<1>();                            // B(kc) landed (per-thread)
        __syncthreads();                         // visibility + buf-reuse guard

        const int st2 = (st + 2 >= 3) ? st - 1 : st + 2;   // (kc+2)%3
        if (kc + 2 < 8) STS_A(st2);              // from pa (chunk kc+2)
        if (kc + 3 < 8) LDG_A(kc + 3);           // -> pa
        if (kc + 2 < 8) STAGE_B(kc + 2, st2);
        cp_commit();                             // uniform group count

        const uint32_t abuf = sb + (uint32_t)st * A_STG_B;
        const uint32_t bbuf = sb + B_OFF3 + (uint32_t)st * B_STG_B;

#pragma unroll
        for (int ks = 0; ks < 4; ++ks) {
            const int k0 = ks * 16;
            uint32_t af[2][4];
#pragma unroll
            for (int mt = 0; mt < 2; ++mt)
                ldm_x4(af[mt], abuf + (uint32_t)(wm * 32 + mt * 16 + a_row) * RBYTES
                                    + (uint32_t)(k0 + a_kof) * 2);
            uint32_t bf[4][4];
#pragma unroll
            for (int p = 0; p < 4; ++p)
                ldm_x4(bf[p], bbuf + (uint32_t)(wn * 64 + p * 16 + b_row) * RBYTES
                                   + (uint32_t)(k0 + b_kof) * 2);
#pragma unroll
            for (int mt = 0; mt < 2; ++mt)
#pragma unroll
                for (int nt = 0; nt < 8; ++nt)
                    mma16816(acc[mt][nt], af[mt],
                             bf[nt >> 1][(nt & 1) * 2], bf[nt >> 1][(nt & 1) * 2 + 1]);
        }
        st = (st + 1 >= 3) ? 0 : st + 1;
    }

    // epilogue: per-row partial of sum_n relu(d + bias[n]) * wc[n]
#pragma unroll
    for (int mt = 0; mt < 2; ++mt) {
        float pr0 = 0.f, pr1 = 0.f;
#pragma unroll
        for (int nt = 0; nt < 8; ++nt) {
            int c = wn * 64 + nt * 8 + 2 * t;
            float b0v = bias_s[c], b1v = bias_s[c + 1];
            float w0v = wc_s[c],   w1v = wc_s[c + 1];
            pr0 += fmaxf(acc[mt][nt][0] + b0v, 0.f) * w0v
                 + fmaxf(acc[mt][nt][1] + b1v, 0.f) * w1v;
            pr1 += fmaxf(acc[mt][nt][2] + b0v, 0.f) * w0v
                 + fmaxf(acc[mt][nt][3] + b1v, 0.f) * w1v;
        }
        pr0 += __shfl_xor_sync(0xffffffffu, pr0, 1);
        pr0 += __shfl_xor_sync(0xffffffffu, pr0, 2);
        pr1 += __shfl_xor_sync(0xffffffffu, pr1, 1);
        pr1 += __shfl_xor_sync(0xffffffffu, pr1, 2);
        if (t == 0) {
            int row = wm * 32 + mt * 16 + g;
            red[row * 4 + wn]       = pr0;
            red[(row + 8) * 4 + wn] = pr1;
        }
    }
    __syncthreads();
    if (tid < 128) {
        float s = red[tid * 4] + red[tid * 4 + 1] + red[tid * 4 + 2] + red[tid * 4 + 3];
        g_scores2[blockIdx.z * (BB * LL) + b * LL + l0 + tid] = s;
    }
#undef LDG_A
#undef STS_A
#undef STAGE_B
}

// ============ Kernel 3: softmax over L + weighted sum (fp32 x) ============
// grid (16 e-chunks of 32, 64 b), 256 threads (more blocks -> latency hiding)
__global__ __launch_bounds__(256)
void ctx_kernel(const float* __restrict__ x, float* __restrict__ out)
{
    __shared__ float sc[LL];
    __shared__ float redw[16];
    __shared__ float part[8][32];

    const int b = blockIdx.y, e0 = blockIdx.x * 32;
    const int tid = threadIdx.x, lane = tid & 31, wid = tid >> 5;

    float lmax = -1e30f;
#pragma unroll
    for (int i = tid; i < LL; i += 256) {
        float v = g_scores2[b * LL + i] + g_scores2[BB * LL + b * LL + i];
        sc[i] = v;
        lmax = fmaxf(lmax, v);
    }
#pragma unroll
    for (int off = 16; off > 0; off >>= 1)
        lmax = fmaxf(lmax, __shfl_xor_sync(0xffffffffu, lmax, off));
    if (lane == 0) redw[wid] = lmax;
    __syncthreads();
    float gmax = redw[0];
#pragma unroll
    for (int j = 1; j < 8; ++j) gmax = fmaxf(gmax, redw[j]);

    float lsum = 0.f;
#pragma unroll
    for (int i = tid; i < LL; i += 256) {
        float e = __expf(sc[i] - gmax);
        sc[i] = e;
        lsum += e;
    }
#pragma unroll
    for (int off = 16; off > 0; off >>= 1)
        lsum += __shfl_xor_sync(0xffffffffu, lsum, off);
    if (lane == 0) redw[8 + wid] = lsum;
    __syncthreads();
    float gsum = 0.f;
#pragma unroll
    for (int j = 0; j < 8; ++j) gsum += redw[8 + j];
    const float inv = 1.0f / gsum;

    const int el = lane, lg = wid;              // 8 L-groups of stride 8
    const float* xp = x + (size_t)b * LL * ENC + e0 + el;
    float acc = 0.f;
#pragma unroll 8
    for (int l = lg; l < LL; l += 8)
        acc += sc[l] * xp[(size_t)l * ENC];
    part[lg][el] = acc;
    __syncthreads();
    if (tid < 32) {
        float s = part[0][tid] + part[1][tid] + part[2][tid] + part[3][tid]
                + part[4][tid] + part[5][tid] + part[6][tid] + part[7][tid];
        out[b * ENC + e0 + tid] = s * inv;
    }
}

// =====================================================================
extern "C" void kernel_launch(void* const* d_in, const int* in_sizes, int n_in,
                              void* d_out, int out_size)
{
    const float* x      = (const float*)d_in[0];
    const float* str    = (const float*)d_in[1];
    const float* cell   = (const float*)d_in[2];
    const float* W_enc  = (const float*)d_in[3];
    const float* b_enc  = (const float*)d_in[4];
    const float* W_str  = (const float*)d_in[5];
    const float* b_str  = (const float*)d_in[6];
    const float* W_cell = (const float*)d_in[7];
    const float* b_cell = (const float*)d_in[8];
    const float* W_comb = (const float*)d_in[9];
    float* out = (float*)d_out;

    cudaFuncSetAttribute(scores_hmma_kernel,
                         cudaFuncAttributeMaxDynamicSharedMemorySize, S_TOTAL);

    prep_kernel<<<320, 256>>>(W_enc, str, cell, W_str, W_cell);
    scores_hmma_kernel<<<dim3(8, BB, 2), 512, S_TOTAL>>>(x, W_comb, b_enc, b_str, b_cell);
    ctx_kernel<<<dim3(16, BB), 256>>>(x, out);
}

// round 17
// speedup vs baseline: 4.9855x; 1.1682x over previous
#include <cuda_runtime.h>
#include <cuda_fp16.h>
#include <cstdint>

#define BB    64
#define LL    1024
#define ENC   512
#define ATTN  512
#define STRH  256
#define CELLH 512
#define NSPLIT 24                               // bias K-splits (768/32)

// ------------------- device scratch (static; no allocs) -------------------
__device__ float g_bpart[NSPLIT * BB * ATTN];   // 3.1 MB
__device__ float g_scores2[2 * BB * LL];
__device__ __align__(16) __half g_wt16[ATTN * ENC];          // W^T fp16

// ------------------- helpers -------------------
__device__ __forceinline__ uint32_t smem_u32(const void* p) {
    uint32_t a;
    asm("{ .reg .u64 t; cvta.to.shared.u64 t, %1; cvt.u32.u64 %0, t; }"
        : "=r"(a) : "l"(p));
    return a;
}
__device__ __forceinline__ void cp16(uint32_t dst, const void* src) {
    asm volatile("cp.async.ca.shared.global [%0], [%1], 16;"
                 :: "r"(dst), "l"(src));
}
__device__ __forceinline__ void cp_commit() {
    asm volatile("cp.async.commit_group;");
}
template <int N>
__device__ __forceinline__ void cp_wait() {
    asm volatile("cp.async.wait_group %0;" :: "n"(N));
}
__device__ __forceinline__ void ldm_x4(uint32_t* r, uint32_t addr) {
    asm volatile("ldmatrix.sync.aligned.m8n8.x4.shared.b16 {%0,%1,%2,%3}, [%4];"
                 : "=r"(r[0]), "=r"(r[1]), "=r"(r[2]), "=r"(r[3]) : "r"(addr));
}
__device__ __forceinline__ void mma16816(float* d, const uint32_t* a,
                                         uint32_t b0, uint32_t b1) {
    asm volatile(
        "mma.sync.aligned.m16n8k16.row.col.f32.f16.f16.f32 "
        "{%0,%1,%2,%3}, {%4,%5,%6,%7}, {%8,%9}, {%0,%1,%2,%3};"
        : "+f"(d[0]), "+f"(d[1]), "+f"(d[2]), "+f"(d[3])
        : "r"(a[0]), "r"(a[1]), "r"(a[2]), "r"(a[3]), "r"(b0), "r"(b1));
}

// ====== Kernel 1 (merged prep): blocks 0..255 convw, 256..447 bias ======
// bias part: K split into 24 chunks of 32 (short dependence chains,
// 192 blocks of latency cover instead of 64).
__global__ __launch_bounds__(256)
void prep_kernel(const float* __restrict__ W,
                 const float* __restrict__ str, const float* __restrict__ cell,
                 const float* __restrict__ Wstr, const float* __restrict__ Wcell)
{
    __shared__ float sh[34 * 65];                 // bias H slice / convw tile
    const int bid = blockIdx.x;
    const int tid = threadIdx.x;

    if (bid < 256) {
        // ---- convw: W_enc -> W^T fp16 (32x32 tile) ----
        float (*t)[33] = (float(*)[33])sh;
        const int n0 = (bid & 15) * 32, k0 = (bid >> 4) * 32;
#pragma unroll
        for (int j = 0; j < 4; ++j) {
            int i = tid + j * 256;
            int r = i >> 5, c = i & 31;
            t[r][c] = W[(k0 + r) * ATTN + n0 + c];
        }
        __syncthreads();
#pragma unroll
        for (int j = 0; j < 4; ++j) {
            int i = tid + j * 256;
            int r = i >> 5, c = i & 31;
            g_wt16[(n0 + r) * ENC + k0 + c] = __float2half_rn(t[c][r]);
        }
        return;
    }

    // ---- bias split-K partials (deterministic), K-chunk = 32 ----
    const int blk = bid - 256;                   // 0..191
    const int ac = blk & 7, es = blk >> 3;       // ac 0..7, es 0..23
    const int a0 = ac * 64, e0 = es * 32;

    // H slice [32 e][64 b] -> smem (stride 65)
#pragma unroll
    for (int j = 0; j < 8; ++j) {
        int idx = tid + j * 256;
        int el = idx >> 6, bb = idx & 63;
        int e = e0 + el;
        sh[el * 65 + bb] = (e < STRH) ? str[bb * STRH + e]
                                      : cell[bb * CELLH + (e - STRH)];
    }
    __syncthreads();

    const int ty = tid >> 4, tx = tid & 15;
    const int b0 = ty * 4, al = a0 + tx * 4;
    float acc[4][4];
#pragma unroll
    for (int i = 0; i < 4; ++i)
#pragma unroll
        for (int j = 0; j < 4; ++j) acc[i][j] = 0.f;

#pragma unroll
    for (int el = 0; el < 32; ++el) {
        int e = e0 + el;
        const float* wr = (e < STRH) ? (Wstr + e * ATTN) : (Wcell + (e - STRH) * ATTN);
        float4 w = *(const float4*)(wr + al);
#pragma unroll
        for (int i = 0; i < 4; ++i) {
            float h = sh[el * 65 + b0 + i];
            acc[i][0] += h * w.x; acc[i][1] += h * w.y;
            acc[i][2] += h * w.z; acc[i][3] += h * w.w;
        }
    }
#pragma unroll
    for (int i = 0; i < 4; ++i) {
        float4 v = make_float4(acc[i][0], acc[i][1], acc[i][2], acc[i][3]);
        *(float4*)(&g_bpart[(es * BB + b0 + i) * ATTN + al]) = v;
    }
}

// ===================== Kernel 2: scores via fp16 HMMA =====================
// grid (8 Ltiles, 64 b, 2 Nhalves), 512 threads (16 warps, 4m x 4n).
// Block tile M=128, N=256, K=512 in 8 chunks of 64. Warp tile 32x64.
// Three-stage pipeline, one __syncthreads per chunk.
#define RSTRIDE   72                          // halfs per smem row (padded)
#define RBYTES    (RSTRIDE * 2)               // 144
#define A_STG_B   (128 * RBYTES)              // 18432
#define B_OFF3    (3 * A_STG_B)               // 55296
#define B_STG_B   (256 * RBYTES)              // 36864
#define BIAS_OFF  (B_OFF3 + 3 * B_STG_B)      // 165888
#define WC_OFF    (BIAS_OFF + 1024)           // 166912
#define RED_OFF   (WC_OFF + 1024)             // 167936
#define S_TOTAL   (RED_OFF + 2048)            // 169984

__global__ __launch_bounds__(512, 1)
void scores_hmma_kernel(const float* __restrict__ x, const float* __restrict__ Wc,
                        const float* __restrict__ benc, const float* __restrict__ bstr,
                        const float* __restrict__ bcell)
{
    extern __shared__ char sm[];
    const uint32_t sb = smem_u32(sm);
    float* bias_s = (float*)(sm + BIAS_OFF);
    float* wc_s   = (float*)(sm + WC_OFF);
    float* red    = (float*)(sm + RED_OFF);                   // [128][4]

    const int tid = threadIdx.x;
    const int wid = tid >> 5, lane = tid & 31;
    const int g = lane >> 2, t = lane & 3;
    const int wm = wid >> 2, wn = wid & 3;                    // 4m x 4n
    const int b = blockIdx.y, l0 = blockIdx.x * 128, n0 = blockIdx.z * 256;

    // bias + wc into smem (folds 24 split-K partials; b_comb dropped)
    if (tid < 256) {
        int a = n0 + tid;
        float bv = benc[a] + bstr[a] + bcell[a];
#pragma unroll
        for (int es = 0; es < NSPLIT; ++es)
            bv += g_bpart[(es * BB + b) * ATTN + a];
        bias_s[tid] = bv;
        wc_s[tid]   = Wc[a];
    }

    const float* xbase = x + ((size_t)(b * LL + l0)) * ENC;
    const __half* bbase = g_wt16 + (size_t)n0 * ENC;

    // A staging: 128 rows x 64 fp32/chunk, 16 floats per thread
    const int a_r = tid >> 2;                  // 0..127
    const int a_c = (tid & 3) * 16;            // 0/16/32/48
    // B staging: 256 rows x 64 halfs/chunk, 4 rows per thread
    const int b_r = tid >> 3, b_q = tid & 7;

    float4 pa[4];
#define LDG_A(c) do { \
    const float* ap = xbase + (size_t)a_r * ENC + (c) * 64 + a_c; \
    pa[0] = *(const float4*)(ap);      pa[1] = *(const float4*)(ap + 4); \
    pa[2] = *(const float4*)(ap + 8);  pa[3] = *(const float4*)(ap + 12); \
} while (0)
#define STS_A(stg) do { \
    char* ad = sm + (stg) * A_STG_B + (uint32_t)a_r * RBYTES + (uint32_t)a_c * 2; \
    _Pragma("unroll") \
    for (int i = 0; i < 4; ++i) { \
        __half2 h0 = __floats2half2_rn(pa[i].x, pa[i].y); \
        __half2 h1 = __floats2half2_rn(pa[i].z, pa[i].w); \
        uint2 o; \
        o.x = *reinterpret_cast<uint32_t*>(&h0); \
        o.y = *reinterpret_cast<uint32_t*>(&h1); \
        *(uint2*)(ad + i * 8) = o; \
    } \
} while (0)
#define STAGE_B(c, stg) do { \
    uint32_t bbuf = sb + B_OFF3 + (uint32_t)(stg) * B_STG_B; \
    _Pragma("unroll") \
    for (int it = 0; it < 4; ++it) { \
        int row = b_r + it * 64; \
        cp16(bbuf + (uint32_t)row * RBYTES + b_q * 16, \
             bbase + (size_t)row * ENC + (c) * 64 + b_q * 8); \
    } \
} while (0)

    // prologue: stage chunks 0,1; preload chunk 2 into regs
    LDG_A(0); STS_A(0);
    LDG_A(1); STS_A(1);
    LDG_A(2);
    STAGE_B(0, 0); cp_commit();
    STAGE_B(1, 1); cp_commit();

    float acc[2][8][4];
#pragma unroll
    for (int i = 0; i < 2; ++i)
#pragma unroll
        for (int j = 0; j < 8; ++j)
#pragma unroll
            for (int k = 0; k < 4; ++k) acc[i][j][k] = 0.f;

    // per-lane ldmatrix address components (proven mapping)
    const int a_row = (lane & 15);
    const int a_kof = (lane >> 4) * 8;
    const int b_row = ((lane >> 4) << 3) + (lane & 7);
    const int b_kof = ((lane >> 3) & 1) * 8;

    int st = 0;                                  // stage index = kc % 3
    for (int kc = 0; kc < 8; ++kc) {
        cp_wait<1>();                            // B(kc) landed
        __syncthreads();                         // visibility + buf-reuse guard

        const int st2 = (st + 2 >= 3) ? st - 1 : st + 2;   // (kc+2)%3
        if (kc + 2 < 8) STS_A(st2);              // from pa (chunk kc+2)
        if (kc + 3 < 8) LDG_A(kc + 3);           // -> pa
        if (kc + 2 < 8) STAGE_B(kc + 2, st2);
        cp_commit();                             // uniform group count

        const uint32_t abuf = sb + (uint32_t)st * A_STG_B;
        const uint32_t bbuf = sb + B_OFF3 + (uint32_t)st * B_STG_B;

#pragma unroll
        for (int ks = 0; ks < 4; ++ks) {
            const int k0 = ks * 16;
            uint32_t af[2][4];
#pragma unroll
            for (int mt = 0; mt < 2; ++mt)
                ldm_x4(af[mt], abuf + (uint32_t)(wm * 32 + mt * 16 + a_row) * RBYTES
                                    + (uint32_t)(k0 + a_kof) * 2);
            uint32_t bf[4][4];
#pragma unroll
            for (int p = 0; p < 4; ++p)
                ldm_x4(bf[p], bbuf + (uint32_t)(wn * 64 + p * 16 + b_row) * RBYTES
                                   + (uint32_t)(k0 + b_kof) * 2);
#pragma unroll
            for (int mt = 0; mt < 2; ++mt)
#pragma unroll
                for (int nt = 0; nt < 8; ++nt)
                    mma16816(acc[mt][nt], af[mt],
                             bf[nt >> 1][(nt & 1) * 2], bf[nt >> 1][(nt & 1) * 2 + 1]);
        }
        st = (st + 1 >= 3) ? 0 : st + 1;
    }

    // epilogue: per-row partial of sum_n relu(d + bias[n]) * wc[n]
#pragma unroll
    for (int mt = 0; mt < 2; ++mt) {
        float pr0 = 0.f, pr1 = 0.f;
#pragma unroll
        for (int nt = 0; nt < 8; ++nt) {
            int c = wn * 64 + nt * 8 + 2 * t;
            float b0v = bias_s[c], b1v = bias_s[c + 1];
            float w0v = wc_s[c],   w1v = wc_s[c + 1];
            pr0 += fmaxf(acc[mt][nt][0] + b0v, 0.f) * w0v
                 + fmaxf(acc[mt][nt][1] + b1v, 0.f) * w1v;
            pr1 += fmaxf(acc[mt][nt][2] + b0v, 0.f) * w0v
                 + fmaxf(acc[mt][nt][3] + b1v, 0.f) * w1v;
        }
        pr0 += __shfl_xor_sync(0xffffffffu, pr0, 1);
        pr0 += __shfl_xor_sync(0xffffffffu, pr0, 2);
        pr1 += __shfl_xor_sync(0xffffffffu, pr1, 1);
        pr1 += __shfl_xor_sync(0xffffffffu, pr1, 2);
        if (t == 0) {
            int row = wm * 32 + mt * 16 + g;
            red[row * 4 + wn]       = pr0;
            red[(row + 8) * 4 + wn] = pr1;
        }
    }
    __syncthreads();
    if (tid < 128) {
        float s = red[tid * 4] + red[tid * 4 + 1] + red[tid * 4 + 2] + red[tid * 4 + 3];
        g_scores2[blockIdx.z * (BB * LL) + b * LL + l0 + tid] = s;
    }
#undef LDG_A
#undef STS_A
#undef STAGE_B
}

// ============ Kernel 3: softmax over L + weighted sum (fp32 x) ============
// grid (16 e-chunks of 32, 64 b), 256 threads
__global__ __launch_bounds__(256)
void ctx_kernel(const float* __restrict__ x, float* __restrict__ out)
{
    __shared__ float sc[LL];
    __shared__ float redw[16];
    __shared__ float part[8][32];

    const int b = blockIdx.y, e0 = blockIdx.x * 32;
    const int tid = threadIdx.x, lane = tid & 31, wid = tid >> 5;

    float lmax = -1e30f;
#pragma unroll
    for (int i = tid; i < LL; i += 256) {
        float v = g_scores2[b * LL + i] + g_scores2[BB * LL + b * LL + i];
        sc[i] = v;
        lmax = fmaxf(lmax, v);
    }
#pragma unroll
    for (int off = 16; off > 0; off >>= 1)
        lmax = fmaxf(lmax, __shfl_xor_sync(0xffffffffu, lmax, off));
    if (lane == 0) redw[wid] = lmax;
    __syncthreads();
    float gmax = redw[0];
#pragma unroll
    for (int j = 1; j < 8; ++j) gmax = fmaxf(gmax, redw[j]);

    float lsum = 0.f;
#pragma unroll
    for (int i = tid; i < LL; i += 256) {
        float e = __expf(sc[i] - gmax);
        sc[i] = e;
        lsum += e;
    }
#pragma unroll
    for (int off = 16; off > 0; off >>= 1)
        lsum += __shfl_xor_sync(0xffffffffu, lsum, off);
    if (lane == 0) redw[8 + wid] = lsum;
    __syncthreads();
    float gsum = 0.f;
#pragma unroll
    for (int j = 0; j < 8; ++j) gsum += redw[8 + j];
    const float inv = 1.0f / gsum;

    const int el = lane, lg = wid;              // 8 L-groups of stride 8
    const float* xp = x + (size_t)b * LL * ENC + e0 + el;
    float acc = 0.f;
#pragma unroll 8
    for (int l = lg; l < LL; l += 8)
        acc += sc[l] * xp[(size_t)l * ENC];
    part[lg][el] = acc;
    __syncthreads();
    if (tid < 32) {
        float s = part[0][tid] + part[1][tid] + part[2][tid] + part[3][tid]
                + part[4][tid] + part[5][tid] + part[6][tid] + part[7][tid];
        out[b * ENC + e0 + tid] = s * inv;
    }
}

// =====================================================================
extern "C" void kernel_launch(void* const* d_in, const int* in_sizes, int n_in,
                              void* d_out, int out_size)
{
    const float* x      = (const float*)d_in[0];
    const float* str    = (const float*)d_in[1];
    const float* cell   = (const float*)d_in[2];
    const float* W_enc  = (const float*)d_in[3];
    const float* b_enc  = (const float*)d_in[4];
    const float* W_str  = (const float*)d_in[5];
    const float* b_str  = (const float*)d_in[6];
    const float* W_cell = (const float*)d_in[7];
    const float* b_cell = (const float*)d_in[8];
    const float* W_comb = (const float*)d_in[9];
    float* out = (float*)d_out;

    cudaFuncSetAttribute(scores_hmma_kernel,
                         cudaFuncAttributeMaxDynamicSharedMemorySize, S_TOTAL);

    prep_kernel<<<448, 256>>>(W_enc, str, cell, W_str, W_cell);
    scores_hmma_kernel<<<dim3(8, BB, 2), 512, S_TOTAL>>>(x, W_comb, b_enc, b_str, b_cell);
    ctx_kernel<<<dim3(16, BB), 256>>>(x, out);
}